// round 7
// baseline (speedup 1.0000x reference)
#include <cuda_runtime.h>
#include <math.h>

#define N      16384
#define IN_F   256
#define OUT_F  128
#define ALPHA  0.2f
#define NEGV   (-9e15f)

#define BM 64
#define BN 32

// Scratch for projected Q, K, V (8 MB each) — device globals, no allocation.
__device__ float g_Q[N * OUT_F];
__device__ float g_K[N * OUT_F];
__device__ float g_V[N * OUT_F];

// ---------------------------------------------------------------------------
// Kernel 1: QKV projection.  grid = (N/64, 3), 256 threads.
// Out[64,128] = h_tile[64,256] @ W[256,128], all fp32.
// Thread tile: 4 rows x 8 cols (16 rowgroups x 16 colgroups).
// ---------------------------------------------------------------------------
__global__ __launch_bounds__(256) void qkv_kernel(
    const float* __restrict__ h,
    const float* __restrict__ Wq,
    const float* __restrict__ Wk,
    const float* __restrict__ Wv)
{
    const float* W   = (blockIdx.y == 0) ? Wq : (blockIdx.y == 1 ? Wk : Wv);
    float*       Out = (blockIdx.y == 0) ? g_Q : (blockIdx.y == 1 ? g_K : g_V);

    __shared__ float hs[64][68];       // 64 rows x 64-k chunk, +4 pad
    __shared__ float ws[64][OUT_F];    // 64 k x 128 cols

    const int tid  = threadIdx.x;
    const int ri   = tid >> 4;         // 0..15 -> rows 4*ri..4*ri+3
    const int ci   = tid & 15;         // 0..15 -> cols 8*ci..8*ci+7
    const int row0 = blockIdx.x * 64;

    float acc[4][8];
#pragma unroll
    for (int a = 0; a < 4; a++)
#pragma unroll
        for (int b = 0; b < 8; b++) acc[a][b] = 0.f;

    for (int kc = 0; kc < IN_F; kc += 64) {
        // hs: 64x64 = 1024 float4, 4 per thread
#pragma unroll
        for (int l = 0; l < 4; l++) {
            int idx = tid + l * 256;
            int r = idx >> 4, c4 = (idx & 15) * 4;
            float4 v = *(const float4*)&h[(row0 + r) * IN_F + kc + c4];
            *(float4*)&hs[r][c4] = v;
        }
        // ws: 64x128 = 2048 float4, 8 per thread
#pragma unroll
        for (int l = 0; l < 8; l++) {
            int idx = tid + l * 256;
            int r = idx >> 5, c4 = (idx & 31) * 4;
            float4 v = *(const float4*)&W[(kc + r) * OUT_F + c4];
            *(float4*)&ws[r][c4] = v;
        }
        __syncthreads();

#pragma unroll 8
        for (int k = 0; k < 64; k++) {
            float a0 = hs[ri * 4 + 0][k];
            float a1 = hs[ri * 4 + 1][k];
            float a2 = hs[ri * 4 + 2][k];
            float a3 = hs[ri * 4 + 3][k];
            float4 b0 = *(const float4*)&ws[k][ci * 8];
            float4 b1 = *(const float4*)&ws[k][ci * 8 + 4];
            float bb[8] = {b0.x, b0.y, b0.z, b0.w, b1.x, b1.y, b1.z, b1.w};
#pragma unroll
            for (int j = 0; j < 8; j++) {
                acc[0][j] = fmaf(a0, bb[j], acc[0][j]);
                acc[1][j] = fmaf(a1, bb[j], acc[1][j]);
                acc[2][j] = fmaf(a2, bb[j], acc[2][j]);
                acc[3][j] = fmaf(a3, bb[j], acc[3][j]);
            }
        }
        __syncthreads();
    }

#pragma unroll
    for (int a = 0; a < 4; a++) {
        int r = row0 + ri * 4 + a;
        float4 v0 = {acc[a][0], acc[a][1], acc[a][2], acc[a][3]};
        float4 v1 = {acc[a][4], acc[a][5], acc[a][6], acc[a][7]};
        *(float4*)&Out[r * OUT_F + ci * 8]     = v0;
        *(float4*)&Out[r * OUT_F + ci * 8 + 4] = v1;
    }
}

// ---------------------------------------------------------------------------
// Kernel 2: fused flash-style attention + leaky-relu + adj mask + softmax
//           + attn@V + ELU.  grid = N/BM = 256 CTAs, 256 threads, 2 CTAs/SM.
//
// Stage 1 (S = Q Kt): thread (ti,tj) = (tid>>4, tid&15) owns rows 4ti..4ti+3,
//                     cols 2tj..2tj+1 of the 64x32 S tile.
// Stage 2 (O += P V): thread (ri,ci) = (tid>>4, tid&15) owns rows 4ri..4ri+3,
//                     dims 8ci..8ci+7.  SAME row ownership as stage 1, so
//                     the online-softmax stats (m, l, rescale) never leave
//                     registers; only P goes through smem.
// ---------------------------------------------------------------------------
struct AttnSmem {
    float Qs[BM][128];   // 32 KB
    float Ks[BN][132];   // padded: row-major reads by 16 distinct rows
    float Vs[BN][128];
    float Ps[BM][36];    // padded to 144 B rows (16B aligned, bank shift 4)
};

__global__ __launch_bounds__(256, 2) void attn_kernel(
    const int* __restrict__ adj,
    float* __restrict__ out)
{
    extern __shared__ char smem_raw[];
    AttnSmem& sm = *reinterpret_cast<AttnSmem*>(smem_raw);

    const int tid  = threadIdx.x;
    const int ti   = tid >> 4;   // row group (4 rows), both stages
    const int tj   = tid & 15;   // stage-1 col group (2 cols)
    const int ci   = tid & 15;   // stage-2 dim group (8 dims)
    const int row0 = blockIdx.x * BM;

    // Load Q tile: 64x128 = 2048 float4, 8 per thread
#pragma unroll
    for (int l = 0; l < 8; l++) {
        int idx = tid + l * 256;
        int r = idx >> 5, c4 = (idx & 31) * 4;
        *(float4*)&sm.Qs[r][c4] = *(const float4*)&g_Q[(row0 + r) * OUT_F + c4];
    }

    const float NEG_INF = __int_as_float(0xff800000);
    float m_[4], l_[4], o_[4][8];
#pragma unroll
    for (int r = 0; r < 4; r++) {
        m_[r] = NEG_INF; l_[r] = 0.f;
#pragma unroll
        for (int d = 0; d < 8; d++) o_[r][d] = 0.f;
    }

    for (int it = 0; it < N / BN; ++it) {
        __syncthreads();   // previous stage-2 done with Vs/Ps

        // Load K,V blocks: 32x128 = 1024 float4 each, 4 per thread each
        const int cb = it * BN;
#pragma unroll
        for (int l = 0; l < 4; l++) {
            int idx = tid + l * 256;
            int r = idx >> 5, c4 = (idx & 31) * 4;
            *(float4*)&sm.Ks[r][c4] = *(const float4*)&g_K[(cb + r) * OUT_F + c4];
            *(float4*)&sm.Vs[r][c4] = *(const float4*)&g_V[(cb + r) * OUT_F + c4];
        }
        __syncthreads();

        // ---- Stage 1: S tile (4 rows x 2 cols per thread) ----
        float s[4][2];
#pragma unroll
        for (int r = 0; r < 4; r++) { s[r][0] = 0.f; s[r][1] = 0.f; }

#pragma unroll 8
        for (int k = 0; k < 128; k += 4) {
            float4 q0 = *(const float4*)&sm.Qs[ti * 4 + 0][k];
            float4 q1 = *(const float4*)&sm.Qs[ti * 4 + 1][k];
            float4 q2 = *(const float4*)&sm.Qs[ti * 4 + 2][k];
            float4 q3 = *(const float4*)&sm.Qs[ti * 4 + 3][k];
            float4 ka = *(const float4*)&sm.Ks[tj * 2 + 0][k];
            float4 kb = *(const float4*)&sm.Ks[tj * 2 + 1][k];
#define DOT4(acc, q, kv) \
            acc = fmaf(q.x, kv.x, acc); acc = fmaf(q.y, kv.y, acc); \
            acc = fmaf(q.z, kv.z, acc); acc = fmaf(q.w, kv.w, acc);
            DOT4(s[0][0], q0, ka) DOT4(s[0][1], q0, kb)
            DOT4(s[1][0], q1, ka) DOT4(s[1][1], q1, kb)
            DOT4(s[2][0], q2, ka) DOT4(s[2][1], q2, kb)
            DOT4(s[3][0], q3, ka) DOT4(s[3][1], q3, kb)
#undef DOT4
        }

        // ---- leaky-relu + adjacency mask ----
        const int gc = cb + tj * 2;
#pragma unroll
        for (int r = 0; r < 4; r++) {
            int2 av = *(const int2*)&adj[(row0 + ti * 4 + r) * N + gc];
            float s0 = s[r][0], s1 = s[r][1];
            s0 = fmaxf(s0, ALPHA * s0);           // leaky relu (works both signs)
            s1 = fmaxf(s1, ALPHA * s1);
            s[r][0] = av.x ? s0 : NEGV;
            s[r][1] = av.y ? s1 : NEGV;
        }

        // ---- online softmax update (reduce across 16 tj lanes) ----
        float scale_[4];
#pragma unroll
        for (int r = 0; r < 4; r++) {
            float mt = fmaxf(s[r][0], s[r][1]);
            mt = fmaxf(mt, __shfl_xor_sync(0xffffffffu, mt, 1));
            mt = fmaxf(mt, __shfl_xor_sync(0xffffffffu, mt, 2));
            mt = fmaxf(mt, __shfl_xor_sync(0xffffffffu, mt, 4));
            mt = fmaxf(mt, __shfl_xor_sync(0xffffffffu, mt, 8));
            float mn = fmaxf(m_[r], mt);
            float fs = __expf(m_[r] - mn);        // -inf first iter -> 0
            float p0 = __expf(s[r][0] - mn);
            float p1 = __expf(s[r][1] - mn);
            float rs = p0 + p1;
            rs += __shfl_xor_sync(0xffffffffu, rs, 1);
            rs += __shfl_xor_sync(0xffffffffu, rs, 2);
            rs += __shfl_xor_sync(0xffffffffu, rs, 4);
            rs += __shfl_xor_sync(0xffffffffu, rs, 8);
            l_[r] = l_[r] * fs + rs;
            m_[r] = mn;
            scale_[r] = fs;
            sm.Ps[ti * 4 + r][tj * 2 + 0] = p0;
            sm.Ps[ti * 4 + r][tj * 2 + 1] = p1;
        }
        __syncthreads();

        // ---- Stage 2: O = O*fs + P@V (4 rows x 8 dims per thread) ----
#pragma unroll
        for (int r = 0; r < 4; r++)
#pragma unroll
            for (int d = 0; d < 8; d++) o_[r][d] *= scale_[r];

#pragma unroll
        for (int c = 0; c < BN; c += 4) {
            float4 P0 = *(const float4*)&sm.Ps[ti * 4 + 0][c];
            float4 P1 = *(const float4*)&sm.Ps[ti * 4 + 1][c];
            float4 P2 = *(const float4*)&sm.Ps[ti * 4 + 2][c];
            float4 P3 = *(const float4*)&sm.Ps[ti * 4 + 3][c];
            float pr[4][4] = {{P0.x, P0.y, P0.z, P0.w},
                              {P1.x, P1.y, P1.z, P1.w},
                              {P2.x, P2.y, P2.z, P2.w},
                              {P3.x, P3.y, P3.z, P3.w}};
#pragma unroll
            for (int cc = 0; cc < 4; cc++) {
                float4 va = *(const float4*)&sm.Vs[c + cc][ci * 8];
                float4 vb = *(const float4*)&sm.Vs[c + cc][ci * 8 + 4];
                float vv[8] = {va.x, va.y, va.z, va.w, vb.x, vb.y, vb.z, vb.w};
#pragma unroll
                for (int r = 0; r < 4; r++)
#pragma unroll
                    for (int d = 0; d < 8; d++)
                        o_[r][d] = fmaf(pr[r][cc], vv[d], o_[r][d]);
            }
        }
    }

    // ---- epilogue: normalize, ELU, store ----
#pragma unroll
    for (int r = 0; r < 4; r++) {
        float inv = 1.f / l_[r];
        int row = row0 + ti * 4 + r;
        float v[8];
#pragma unroll
        for (int d = 0; d < 8; d++) {
            float x = o_[r][d] * inv;
            v[d] = (x > 0.f) ? x : (__expf(x) - 1.f);
        }
        float4 v0 = {v[0], v[1], v[2], v[3]};
        float4 v1 = {v[4], v[5], v[6], v[7]};
        *(float4*)&out[row * OUT_F + ci * 8]     = v0;
        *(float4*)&out[row * OUT_F + ci * 8 + 4] = v1;
    }
}

// ---------------------------------------------------------------------------
extern "C" void kernel_launch(void* const* d_in, const int* in_sizes, int n_in,
                              void* d_out, int out_size)
{
    const float* h   = (const float*)d_in[0];
    const int*   adj = (const int*)  d_in[1];
    const float* Wq  = (const float*)d_in[2];
    const float* Wk  = (const float*)d_in[3];
    const float* Wv  = (const float*)d_in[4];
    float*       out = (float*)d_out;

    (void)in_sizes; (void)n_in; (void)out_size;

    const int smem_bytes = (int)sizeof(AttnSmem);
    cudaFuncSetAttribute(attn_kernel,
                         cudaFuncAttributeMaxDynamicSharedMemorySize,
                         smem_bytes);

    qkv_kernel<<<dim3(N / 64, 3), 256>>>(h, Wq, Wk, Wv);
    attn_kernel<<<N / BM, 256, smem_bytes>>>(adj, out);
}